// round 1
// baseline (speedup 1.0000x reference)
#include <cuda_runtime.h>
#include <math.h>

#define BB 16
#define TT 2048
#define CC 768
#define HH 128

// Scratch for projected Q, K, V: [B][T][H] each (fp32). Static __device__
// arrays (no allocation) per harness rules.
__device__ float g_q[BB * TT * HH];
__device__ float g_k[BB * TT * HH];
__device__ float g_v[BB * TT * HH];

// ---------------------------------------------------------------------------
// Kernel 1: QKV projection. Y = X @ W, X:[32768,768], W:[768,128].
// Grid: (M/64, 128/64, 3) ; block 256 (16x16), 4x4 register tile, BK=16.
// blockIdx.z selects Wq/Wk/Wv and the output buffer.
// ---------------------------------------------------------------------------
__global__ __launch_bounds__(256) void qkv_kernel(
    const float* __restrict__ x,
    const float* __restrict__ Wq,
    const float* __restrict__ Wk,
    const float* __restrict__ Wv)
{
    __shared__ float As[16][65];   // [k][m], padded
    __shared__ float Bs[16][64];   // [k][n]

    const float* W   = (blockIdx.z == 0) ? Wq : (blockIdx.z == 1) ? Wk : Wv;
    float*       out = (blockIdx.z == 0) ? g_q : (blockIdx.z == 1) ? g_k : g_v;

    const int m0 = blockIdx.x * 64;
    const int n0 = blockIdx.y * 64;
    const int tid = threadIdx.x;
    const int tx = tid & 15;
    const int ty = tid >> 4;

    float acc[4][4] = {};

    for (int kt = 0; kt < CC; kt += 16) {
        // Load A tile [64 rows x 16 k] transposed into As[k][m]
        {
            const int m  = tid >> 2;            // 0..63
            const int k4 = (tid & 3) << 2;      // 0,4,8,12
            float4 a = *reinterpret_cast<const float4*>(
                &x[(size_t)(m0 + m) * CC + kt + k4]);
            As[k4 + 0][m] = a.x;
            As[k4 + 1][m] = a.y;
            As[k4 + 2][m] = a.z;
            As[k4 + 3][m] = a.w;
        }
        // Load B tile [16 k x 64 n]
        {
            const int k  = tid >> 4;            // 0..15
            const int n4 = (tid & 15) << 2;     // 0..60
            float4 b = *reinterpret_cast<const float4*>(
                &W[(size_t)(kt + k) * HH + n0 + n4]);
            *reinterpret_cast<float4*>(&Bs[k][n4]) = b;
        }
        __syncthreads();

        #pragma unroll
        for (int kk = 0; kk < 16; kk++) {
            float a[4], b[4];
            #pragma unroll
            for (int i = 0; i < 4; i++) a[i] = As[kk][ty + 16 * i];
            #pragma unroll
            for (int j = 0; j < 4; j++) b[j] = Bs[kk][tx + 16 * j];
            #pragma unroll
            for (int i = 0; i < 4; i++)
                #pragma unroll
                for (int j = 0; j < 4; j++)
                    acc[i][j] += a[i] * b[j];
        }
        __syncthreads();
    }

    #pragma unroll
    for (int i = 0; i < 4; i++)
        #pragma unroll
        for (int j = 0; j < 4; j++)
            out[(size_t)(m0 + ty + 16 * i) * HH + n0 + tx + 16 * j] = acc[i][j];
}

// ---------------------------------------------------------------------------
// Kernel 2: causal flash attention, one CTA per (batch, 64-row Q tile).
// 256 threads (16x16). Thread owns rows r = ty+16i (i<4), and for S it owns
// cols c = tx+16j (j<4); for PV/output it owns head-dims hd = tx+16j (j<8).
// Stride-16 mapping keeps shared reads conflict-free / 2-way max.
// Online softmax; scale applied before masking (equivalent to reference).
// ---------------------------------------------------------------------------
__global__ __launch_bounds__(256) void attn_kernel(float* __restrict__ out)
{
    extern __shared__ float sm[];
    float* Qs = sm;                      // [64][128]
    float* Ks = Qs + 64 * 128;           // [64][132] (padded)
    float* Vs = Ks + 64 * 132;           // [64][128]
    float* Ps = Vs + 64 * 128;           // [64][68]  (padded)

    const int b  = blockIdx.y;
    const int qt = (int)gridDim.x - 1 - (int)blockIdx.x;  // heavy tiles first
    const int q0 = qt * 64;
    const int tid = threadIdx.x;
    const int tx = tid & 15;
    const int ty = tid >> 4;

    const float scale = 0.03608439182435161f;  // 768^-0.5

    // Load Q tile
    {
        const float* qg = g_q + ((size_t)b * TT + q0) * HH;
        #pragma unroll
        for (int it = 0; it < 8; it++) {
            int i = tid + it * 256;           // 0..2047 float4 chunks
            int r  = i >> 5;
            int h4 = (i & 31) << 2;
            *reinterpret_cast<float4*>(&Qs[r * 128 + h4]) =
                *reinterpret_cast<const float4*>(&qg[(size_t)r * HH + h4]);
        }
    }

    float m_i[4], l_i[4], acc[4][8];
    #pragma unroll
    for (int i = 0; i < 4; i++) {
        m_i[i] = -INFINITY;
        l_i[i] = 0.0f;
        #pragma unroll
        for (int j = 0; j < 8; j++) acc[i][j] = 0.0f;
    }

    const int nkt = qt + 1;
    for (int kt = 0; kt < nkt; kt++) {
        const int k0 = kt * 64;
        const float* kg = g_k + ((size_t)b * TT + k0) * HH;
        const float* vg = g_v + ((size_t)b * TT + k0) * HH;

        __syncthreads();   // previous iteration done with Ks/Vs
        #pragma unroll
        for (int it = 0; it < 8; it++) {
            int i = tid + it * 256;
            int r  = i >> 5;
            int h4 = (i & 31) << 2;
            *reinterpret_cast<float4*>(&Ks[r * 132 + h4]) =
                *reinterpret_cast<const float4*>(&kg[(size_t)r * HH + h4]);
            *reinterpret_cast<float4*>(&Vs[r * 128 + h4]) =
                *reinterpret_cast<const float4*>(&vg[(size_t)r * HH + h4]);
        }
        __syncthreads();

        // S = Q K^T  (this thread: rows ty+16i, cols tx+16j)
        float s[4][4] = {};
        #pragma unroll 4
        for (int h = 0; h < 128; h += 4) {
            float4 qv[4], kv[4];
            #pragma unroll
            for (int i = 0; i < 4; i++)
                qv[i] = *reinterpret_cast<const float4*>(&Qs[(ty + 16 * i) * 128 + h]);
            #pragma unroll
            for (int j = 0; j < 4; j++)
                kv[j] = *reinterpret_cast<const float4*>(&Ks[(tx + 16 * j) * 132 + h]);
            #pragma unroll
            for (int i = 0; i < 4; i++)
                #pragma unroll
                for (int j = 0; j < 4; j++) {
                    s[i][j] += qv[i].x * kv[j].x;
                    s[i][j] += qv[i].y * kv[j].y;
                    s[i][j] += qv[i].z * kv[j].z;
                    s[i][j] += qv[i].w * kv[j].w;
                }
        }

        const bool diag = (kt == qt);

        // Online softmax per owned row
        #pragma unroll
        for (int i = 0; i < 4; i++) {
            const int r_l = ty + 16 * i;
            float mx = -INFINITY;
            #pragma unroll
            for (int j = 0; j < 4; j++) {
                const int c_l = tx + 16 * j;
                float sv = s[i][j] * scale;
                if (diag && c_l > r_l) sv = -INFINITY;
                s[i][j] = sv;
                mx = fmaxf(mx, sv);
            }
            // reduce max across the 16 tx lanes (xor over lower 4 bits)
            #pragma unroll
            for (int o = 1; o < 16; o <<= 1)
                mx = fmaxf(mx, __shfl_xor_sync(0xffffffffu, mx, o));

            const float m_new = fmaxf(m_i[i], mx);
            const float corr  = __expf(m_i[i] - m_new);  // 0 when m_i=-inf

            float l_add = 0.0f;
            #pragma unroll
            for (int j = 0; j < 4; j++) {
                float p = __expf(s[i][j] - m_new);       // 0 for masked
                s[i][j] = p;
                l_add += p;
            }
            #pragma unroll
            for (int o = 1; o < 16; o <<= 1)
                l_add += __shfl_xor_sync(0xffffffffu, l_add, o);

            l_i[i] = l_i[i] * corr + l_add;
            m_i[i] = m_new;
            #pragma unroll
            for (int j = 0; j < 8; j++) acc[i][j] *= corr;

            // stage P tile to shared
            #pragma unroll
            for (int j = 0; j < 4; j++)
                Ps[r_l * 68 + tx + 16 * j] = s[i][j];
        }
        __syncthreads();

        // O += P @ V   (rows ty+16i, head-dims tx+16j, j<8)
        #pragma unroll 2
        for (int c = 0; c < 64; c++) {
            float p[4];
            #pragma unroll
            for (int i = 0; i < 4; i++)
                p[i] = Ps[(ty + 16 * i) * 68 + c];
            float vv[8];
            #pragma unroll
            for (int j = 0; j < 8; j++)
                vv[j] = Vs[c * 128 + tx + 16 * j];
            #pragma unroll
            for (int i = 0; i < 4; i++)
                #pragma unroll
                for (int j = 0; j < 8; j++)
                    acc[i][j] += p[i] * vv[j];
        }
    }

    // Epilogue: normalize and write
    float* og = out + ((size_t)b * TT + q0) * HH;
    #pragma unroll
    for (int i = 0; i < 4; i++) {
        const float inv = 1.0f / l_i[i];
        #pragma unroll
        for (int j = 0; j < 8; j++)
            og[(size_t)(ty + 16 * i) * HH + tx + 16 * j] = acc[i][j] * inv;
    }
}

// ---------------------------------------------------------------------------
// Launch
// ---------------------------------------------------------------------------
extern "C" void kernel_launch(void* const* d_in, const int* in_sizes, int n_in,
                              void* d_out, int out_size)
{
    const float* x  = (const float*)d_in[0];
    const float* Wq = (const float*)d_in[1];
    const float* Wk = (const float*)d_in[2];
    const float* Wv = (const float*)d_in[3];
    float* out = (float*)d_out;

    const int smem_bytes = (64 * 128 + 64 * 132 + 64 * 128 + 64 * 68) * 4; // 116736
    cudaFuncSetAttribute(attn_kernel,
                         cudaFuncAttributeMaxDynamicSharedMemorySize,
                         smem_bytes);

    // QKV projection: M=32768, N=128 (x2 tiles), 3 weight matrices
    qkv_kernel<<<dim3(TT * BB / 64, 2, 3), 256>>>(x, Wq, Wk, Wv);

    // Attention: one CTA per (q-tile, batch)
    attn_kernel<<<dim3(TT / 64, BB), 256, smem_bytes>>>(out);
}

// round 3
// speedup vs baseline: 2.8547x; 2.8547x over previous
#include <cuda_runtime.h>
#include <cstdint>
#include <math.h>

#define BB 16
#define TT 2048
#define CC 768
#define HH 128

// Scratch for projected Q, K, V: [B][T][H] each (fp32 bits holding tf32-rounded values).
__device__ float g_q[BB * TT * HH];
__device__ float g_k[BB * TT * HH];
__device__ float g_v[BB * TT * HH];

// ---------------------------------------------------------------------------
// helpers
// ---------------------------------------------------------------------------
__device__ __forceinline__ uint32_t f2tf(float f) {
    uint32_t u;
    asm("cvt.rna.tf32.f32 %0, %1;" : "=r"(u) : "f"(f));
    return u;
}

// D += A * B   (m16n8k8, tf32 inputs, fp32 accum)
__device__ __forceinline__ void mma8(float* d, const uint32_t* a, const uint32_t* b) {
    asm volatile(
        "mma.sync.aligned.m16n8k8.row.col.f32.tf32.tf32.f32 "
        "{%0,%1,%2,%3}, {%4,%5,%6,%7}, {%8,%9}, {%0,%1,%2,%3};"
        : "+f"(d[0]), "+f"(d[1]), "+f"(d[2]), "+f"(d[3])
        : "r"(a[0]), "r"(a[1]), "r"(a[2]), "r"(a[3]),
          "r"(b[0]), "r"(b[1]));
}

// ===========================================================================
// Kernel 1: QKV projection via mma.sync tf32.
// Grid (256, 3): blockIdx.x = 128-row M tile, blockIdx.y selects Wq/Wk/Wv.
// CTA tile 128x128, K chunks of 32, double-buffered smem, register prefetch.
// 8 warps: warpRow = wid&3 (32 rows each), warpCol = wid>>2 (64 cols each).
// ===========================================================================
#define NCH 24   // 768 / 32

#define AS_STRIDE 36
#define BS_STRIDE 132
#define AS_BUF (128 * AS_STRIDE)
#define BS_BUF (32 * BS_STRIDE)
#define QKV_SMEM ((2 * AS_BUF + 2 * BS_BUF) * 4)

__global__ __launch_bounds__(256) void qkv_mma_kernel(
    const float* __restrict__ x,
    const float* __restrict__ Wq,
    const float* __restrict__ Wk,
    const float* __restrict__ Wv)
{
    extern __shared__ uint32_t sm_u[];
    uint32_t* As = sm_u;                  // [2][128][36]
    uint32_t* Bs = sm_u + 2 * AS_BUF;     // [2][32][132]

    const int tid  = threadIdx.x;
    const int wid  = tid >> 5;
    const int lane = tid & 31;
    const int g = lane >> 2;     // 0..7
    const int t = lane & 3;      // 0..3
    const int wr = wid & 3;      // warp row (32 rows)
    const int wc = wid >> 2;     // warp col (64 cols)
    const int m0 = blockIdx.x * 128;

    const float* W   = (blockIdx.y == 0) ? Wq : (blockIdx.y == 1) ? Wk : Wv;
    float*       outw = (blockIdx.y == 0) ? g_q : (blockIdx.y == 1) ? g_k : g_v;

    float acc[2][8][4];
    #pragma unroll
    for (int mt = 0; mt < 2; mt++)
        #pragma unroll
        for (int nt = 0; nt < 8; nt++)
            #pragma unroll
            for (int e = 0; e < 4; e++) acc[mt][nt][e] = 0.0f;

    float4 ra[4], rb[4];

    // ---- prologue: load + stage chunk 0 ----
    {
        const float* xg = x + (size_t)m0 * CC;
        #pragma unroll
        for (int p = 0; p < 4; p++) {
            int idx = tid + p * 256;
            int m = idx >> 3, k4 = (idx & 7) << 2;
            ra[p] = *reinterpret_cast<const float4*>(&xg[(size_t)m * CC + k4]);
            int k = idx >> 5, n4 = (idx & 31) << 2;
            rb[p] = *reinterpret_cast<const float4*>(&W[(size_t)k * HH + n4]);
        }
        #pragma unroll
        for (int p = 0; p < 4; p++) {
            int idx = tid + p * 256;
            int m = idx >> 3, k4 = (idx & 7) << 2;
            uint32_t* d = &As[m * AS_STRIDE + k4];
            d[0] = f2tf(ra[p].x); d[1] = f2tf(ra[p].y);
            d[2] = f2tf(ra[p].z); d[3] = f2tf(ra[p].w);
            int k = idx >> 5, n4 = (idx & 31) << 2;
            uint32_t* e = &Bs[k * BS_STRIDE + n4];
            e[0] = f2tf(rb[p].x); e[1] = f2tf(rb[p].y);
            e[2] = f2tf(rb[p].z); e[3] = f2tf(rb[p].w);
        }
    }
    __syncthreads();

    for (int c = 0; c < NCH; c++) {
        const int buf = c & 1;

        // prefetch next chunk into registers
        if (c + 1 < NCH) {
            const float* xg = x + (size_t)m0 * CC + (c + 1) * 32;
            const float* wg = W + (size_t)(c + 1) * 32 * HH;
            #pragma unroll
            for (int p = 0; p < 4; p++) {
                int idx = tid + p * 256;
                int m = idx >> 3, k4 = (idx & 7) << 2;
                ra[p] = *reinterpret_cast<const float4*>(&xg[(size_t)m * CC + k4]);
                int k = idx >> 5, n4 = (idx & 31) << 2;
                rb[p] = *reinterpret_cast<const float4*>(&wg[(size_t)k * HH + n4]);
            }
        }

        // compute on current buffer
        const uint32_t* Ab = As + buf * AS_BUF;
        const uint32_t* Bb = Bs + buf * BS_BUF;
        #pragma unroll
        for (int ks = 0; ks < 4; ks++) {
            uint32_t afr[2][4];
            #pragma unroll
            for (int mt = 0; mt < 2; mt++) {
                int rbase = wr * 32 + mt * 16;
                int k = ks * 8 + t;
                afr[mt][0] = Ab[(rbase + g)     * AS_STRIDE + k];
                afr[mt][1] = Ab[(rbase + g + 8) * AS_STRIDE + k];
                afr[mt][2] = Ab[(rbase + g)     * AS_STRIDE + k + 4];
                afr[mt][3] = Ab[(rbase + g + 8) * AS_STRIDE + k + 4];
            }
            #pragma unroll
            for (int nt = 0; nt < 8; nt++) {
                int n = wc * 64 + nt * 8 + g;
                uint32_t bfr[2];
                bfr[0] = Bb[(ks * 8 + t)     * BS_STRIDE + n];
                bfr[1] = Bb[(ks * 8 + t + 4) * BS_STRIDE + n];
                mma8(acc[0][nt], afr[0], bfr);
                mma8(acc[1][nt], afr[1], bfr);
            }
        }

        // stage next chunk
        if (c + 1 < NCH) {
            uint32_t* Ad = As + ((c + 1) & 1) * AS_BUF;
            uint32_t* Bd = Bs + ((c + 1) & 1) * BS_BUF;
            #pragma unroll
            for (int p = 0; p < 4; p++) {
                int idx = tid + p * 256;
                int m = idx >> 3, k4 = (idx & 7) << 2;
                uint32_t* d = &Ad[m * AS_STRIDE + k4];
                d[0] = f2tf(ra[p].x); d[1] = f2tf(ra[p].y);
                d[2] = f2tf(ra[p].z); d[3] = f2tf(ra[p].w);
                int k = idx >> 5, n4 = (idx & 31) << 2;
                uint32_t* e = &Bd[k * BS_STRIDE + n4];
                e[0] = f2tf(rb[p].x); e[1] = f2tf(rb[p].y);
                e[2] = f2tf(rb[p].z); e[3] = f2tf(rb[p].w);
            }
        }
        __syncthreads();
    }

    // ---- epilogue ----
    #pragma unroll
    for (int mt = 0; mt < 2; mt++) {
        int r0 = m0 + wr * 32 + mt * 16 + g;
        #pragma unroll
        for (int nt = 0; nt < 8; nt++) {
            int col = wc * 64 + nt * 8 + 2 * t;
            *reinterpret_cast<float2*>(&outw[(size_t)r0 * HH + col]) =
                make_float2(acc[mt][nt][0], acc[mt][nt][1]);
            *reinterpret_cast<float2*>(&outw[(size_t)(r0 + 8) * HH + col]) =
                make_float2(acc[mt][nt][2], acc[mt][nt][3]);
        }
    }
}

// ===========================================================================
// Kernel 2: causal flash attention via mma.sync tf32.
// CTA per (64-row Q tile, batch). 256 threads, 8 warps.
// S phase: warps 4 rows x 2 cols (S tile 64x64); PV: 4 rows x 2 H-halves.
// ===========================================================================
#define QS_STRIDE 132
#define PS_STRIDE 68
// floats: Qs + Ks + Vs (64*132 each) + Ps (64*68) + corr(64) + l(64)
#define ATTN_SMEM ((64 * QS_STRIDE * 3 + 64 * PS_STRIDE + 128) * 4)

__global__ __launch_bounds__(256) void attn_mma_kernel(float* __restrict__ out)
{
    extern __shared__ float smf[];
    float* Qs = smf;                       // [64][132]
    float* Ks = Qs + 64 * QS_STRIDE;       // [64][132]
    float* Vs = Ks + 64 * QS_STRIDE;       // [64][132]
    float* Ps = Vs + 64 * QS_STRIDE;       // [64][68]
    float* rc = Ps + 64 * PS_STRIDE;       // [64] row corr
    float* rl = rc + 64;                   // [64] row l

    const int b  = blockIdx.y;
    const int qt = (int)gridDim.x - 1 - (int)blockIdx.x;  // heavy tiles first
    const int q0 = qt * 64;
    const int tid  = threadIdx.x;
    const int wid  = tid >> 5;
    const int lane = tid & 31;
    const int g = lane >> 2;
    const int t = lane & 3;
    const int wr = wid & 3;      // warp row: 16 S-rows
    const int wc = wid >> 2;     // warp col: 32 S-cols / 64 H-cols

    const float scale = 0.03608439182435161f;  // 768^-0.5

    // ---- load Q tile (tf32-rounded) ----
    {
        const float* qg = g_q + ((size_t)b * TT + q0) * HH;
        #pragma unroll
        for (int p = 0; p < 8; p++) {
            int idx = tid + p * 256;
            int r = idx >> 5, h4 = (idx & 31) << 2;
            float4 v = *reinterpret_cast<const float4*>(&qg[(size_t)r * HH + h4]);
            float* d = &Qs[r * QS_STRIDE + h4];
            d[0] = __uint_as_float(f2tf(v.x));
            d[1] = __uint_as_float(f2tf(v.y));
            d[2] = __uint_as_float(f2tf(v.z));
            d[3] = __uint_as_float(f2tf(v.w));
        }
    }

    // softmax row state (thread owns row tid>>2, replicated x4)
    const int r_s = tid >> 2;
    const int qd  = tid & 3;
    float m_i = -INFINITY, l_i = 0.0f;

    // O accumulators: warp tile 16 rows x 64 H-cols = 8 n-tiles
    float oacc[8][4];
    #pragma unroll
    for (int nt = 0; nt < 8; nt++)
        #pragma unroll
        for (int e = 0; e < 4; e++) oacc[nt][e] = 0.0f;

    const int nkt = qt + 1;
    for (int kt = 0; kt < nkt; kt++) {
        __syncthreads();   // previous iteration fully consumed Ks/Vs/Ps

        // ---- stage K & V tiles ----
        {
            const float* kg = g_k + ((size_t)b * TT + (size_t)kt * 64) * HH;
            const float* vg = g_v + ((size_t)b * TT + (size_t)kt * 64) * HH;
            #pragma unroll
            for (int p = 0; p < 8; p++) {
                int idx = tid + p * 256;
                int r = idx >> 5, h4 = (idx & 31) << 2;
                float4 kv = *reinterpret_cast<const float4*>(&kg[(size_t)r * HH + h4]);
                float4 vv = *reinterpret_cast<const float4*>(&vg[(size_t)r * HH + h4]);
                float* dk = &Ks[r * QS_STRIDE + h4];
                dk[0] = __uint_as_float(f2tf(kv.x));
                dk[1] = __uint_as_float(f2tf(kv.y));
                dk[2] = __uint_as_float(f2tf(kv.z));
                dk[3] = __uint_as_float(f2tf(kv.w));
                float* dv = &Vs[r * QS_STRIDE + h4];
                dv[0] = __uint_as_float(f2tf(vv.x));
                dv[1] = __uint_as_float(f2tf(vv.y));
                dv[2] = __uint_as_float(f2tf(vv.z));
                dv[3] = __uint_as_float(f2tf(vv.w));
            }
        }
        __syncthreads();

        // ---- S = Q K^T (warp: rows wr*16.., cols wc*32..) ----
        float sacc[4][4];
        #pragma unroll
        for (int nt = 0; nt < 4; nt++)
            #pragma unroll
            for (int e = 0; e < 4; e++) sacc[nt][e] = 0.0f;

        const uint32_t* Qu = reinterpret_cast<const uint32_t*>(Qs);
        const uint32_t* Ku = reinterpret_cast<const uint32_t*>(Ks);
        #pragma unroll
        for (int ks = 0; ks < 16; ks++) {
            const int k = ks * 8 + t;
            uint32_t afr[4];
            const int rb_ = wr * 16;
            afr[0] = Qu[(rb_ + g)     * QS_STRIDE + k];
            afr[1] = Qu[(rb_ + g + 8) * QS_STRIDE + k];
            afr[2] = Qu[(rb_ + g)     * QS_STRIDE + k + 4];
            afr[3] = Qu[(rb_ + g + 8) * QS_STRIDE + k + 4];
            #pragma unroll
            for (int nt = 0; nt < 4; nt++) {
                const int n = wc * 32 + nt * 8 + g;
                uint32_t bfr[2];
                bfr[0] = Ku[n * QS_STRIDE + k];
                bfr[1] = Ku[n * QS_STRIDE + k + 4];
                mma8(sacc[nt], afr, bfr);
            }
        }

        // ---- write scaled + masked S to Ps ----
        const bool diag = (kt == qt);
        {
            const int rl0 = wr * 16 + g;
            const int rl1 = rl0 + 8;
            #pragma unroll
            for (int nt = 0; nt < 4; nt++) {
                const int cl = wc * 32 + nt * 8 + 2 * t;
                float s0 = sacc[nt][0] * scale;
                float s1 = sacc[nt][1] * scale;
                float s2 = sacc[nt][2] * scale;
                float s3 = sacc[nt][3] * scale;
                if (diag) {
                    if (cl     > rl0) s0 = -INFINITY;
                    if (cl + 1 > rl0) s1 = -INFINITY;
                    if (cl     > rl1) s2 = -INFINITY;
                    if (cl + 1 > rl1) s3 = -INFINITY;
                }
                *reinterpret_cast<float2*>(&Ps[rl0 * PS_STRIDE + cl]) = make_float2(s0, s1);
                *reinterpret_cast<float2*>(&Ps[rl1 * PS_STRIDE + cl]) = make_float2(s2, s3);
            }
        }
        __syncthreads();

        // ---- online softmax (4 threads per row, 16 cols each) ----
        {
            float v[16];
            #pragma unroll
            for (int j = 0; j < 4; j++) {
                float4 x4 = *reinterpret_cast<const float4*>(
                    &Ps[r_s * PS_STRIDE + qd * 16 + j * 4]);
                v[4 * j + 0] = x4.x; v[4 * j + 1] = x4.y;
                v[4 * j + 2] = x4.z; v[4 * j + 3] = x4.w;
            }
            float mx = -INFINITY;
            #pragma unroll
            for (int j = 0; j < 16; j++) mx = fmaxf(mx, v[j]);
            mx = fmaxf(mx, __shfl_xor_sync(0xffffffffu, mx, 1));
            mx = fmaxf(mx, __shfl_xor_sync(0xffffffffu, mx, 2));

            const float m_new = fmaxf(m_i, mx);
            const float corr  = __expf(m_i - m_new);

            float sum = 0.0f;
            #pragma unroll
            for (int j = 0; j < 16; j++) {
                v[j] = __expf(v[j] - m_new);
                sum += v[j];
            }
            sum += __shfl_xor_sync(0xffffffffu, sum, 1);
            sum += __shfl_xor_sync(0xffffffffu, sum, 2);

            l_i = l_i * corr + sum;
            m_i = m_new;

            #pragma unroll
            for (int j = 0; j < 4; j++) {
                float4 x4;
                x4.x = __uint_as_float(f2tf(v[4 * j + 0]));
                x4.y = __uint_as_float(f2tf(v[4 * j + 1]));
                x4.z = __uint_as_float(f2tf(v[4 * j + 2]));
                x4.w = __uint_as_float(f2tf(v[4 * j + 3]));
                *reinterpret_cast<float4*>(&Ps[r_s * PS_STRIDE + qd * 16 + j * 4]) = x4;
            }
            if (qd == 0) rc[r_s] = corr;
        }
        __syncthreads();

        // ---- rescale O accumulators ----
        {
            const float f0 = rc[wr * 16 + g];
            const float f1 = rc[wr * 16 + g + 8];
            #pragma unroll
            for (int nt = 0; nt < 8; nt++) {
                oacc[nt][0] *= f0; oacc[nt][1] *= f0;
                oacc[nt][2] *= f1; oacc[nt][3] *= f1;
            }
        }

        // ---- O += P V (warp: rows wr*16.., H-cols wc*64..) ----
        {
            const uint32_t* Pu = reinterpret_cast<const uint32_t*>(Ps);
            const uint32_t* Vu = reinterpret_cast<const uint32_t*>(Vs);
            #pragma unroll
            for (int ks = 0; ks < 8; ks++) {
                const int k = ks * 8 + t;
                uint32_t afr[4];
                const int rb_ = wr * 16;
                afr[0] = Pu[(rb_ + g)     * PS_STRIDE + k];
                afr[1] = Pu[(rb_ + g + 8) * PS_STRIDE + k];
                afr[2] = Pu[(rb_ + g)     * PS_STRIDE + k + 4];
                afr[3] = Pu[(rb_ + g + 8) * PS_STRIDE + k + 4];
                #pragma unroll
                for (int nt = 0; nt < 8; nt++) {
                    const int n = wc * 64 + nt * 8 + g;
                    uint32_t bfr[2];
                    bfr[0] = Vu[(k)     * QS_STRIDE + n];
                    bfr[1] = Vu[(k + 4) * QS_STRIDE + n];
                    mma8(oacc[nt], afr, bfr);
                }
            }
        }
    }

    // ---- epilogue ----
    __syncthreads();
    if (qd == 0) rl[r_s] = l_i;
    __syncthreads();

    {
        const int r0 = wr * 16 + g;
        const int r1 = r0 + 8;
        const float inv0 = 1.0f / rl[r0];
        const float inv1 = 1.0f / rl[r1];
        float* og = out + ((size_t)b * TT + q0) * HH;
        #pragma unroll
        for (int nt = 0; nt < 8; nt++) {
            const int col = wc * 64 + nt * 8 + 2 * t;
            *reinterpret_cast<float2*>(&og[(size_t)r0 * HH + col]) =
                make_float2(oacc[nt][0] * inv0, oacc[nt][1] * inv0);
            *reinterpret_cast<float2*>(&og[(size_t)r1 * HH + col]) =
                make_float2(oacc[nt][2] * inv1, oacc[nt][3] * inv1);
        }
    }
}

// ===========================================================================
// Launch
// ===========================================================================
extern "C" void kernel_launch(void* const* d_in, const int* in_sizes, int n_in,
                              void* d_out, int out_size)
{
    const float* x  = (const float*)d_in[0];
    const float* Wq = (const float*)d_in[1];
    const float* Wk = (const float*)d_in[2];
    const float* Wv = (const float*)d_in[3];
    float* out = (float*)d_out;

    cudaFuncSetAttribute(qkv_mma_kernel,
                         cudaFuncAttributeMaxDynamicSharedMemorySize, QKV_SMEM);
    cudaFuncSetAttribute(attn_mma_kernel,
                         cudaFuncAttributeMaxDynamicSharedMemorySize, ATTN_SMEM);

    qkv_mma_kernel<<<dim3(TT * BB / 128, 3), 256, QKV_SMEM>>>(x, Wq, Wk, Wv);
    attn_mma_kernel<<<dim3(TT / 64, BB), 256, ATTN_SMEM>>>(out);
}

// round 4
// speedup vs baseline: 3.6992x; 1.2958x over previous
#include <cuda_runtime.h>
#include <cstdint>
#include <math.h>

#define BB 16
#define TT 2048
#define CC 768
#define HH 128

// Scratch for projected Q, K, V: [B][T][H] each (fp32).
__device__ float g_q[BB * TT * HH];
__device__ float g_k[BB * TT * HH];
__device__ float g_v[BB * TT * HH];

// ---------------------------------------------------------------------------
// helpers
// ---------------------------------------------------------------------------
__device__ __forceinline__ uint32_t f2tf(float f) {
    uint32_t u;
    asm("cvt.rna.tf32.f32 %0, %1;" : "=r"(u) : "f"(f));
    return u;
}

// D += A * B   (m16n8k8, tf32 inputs, fp32 accum)
__device__ __forceinline__ void mma8(float* d, const uint32_t* a, const uint32_t* b) {
    asm volatile(
        "mma.sync.aligned.m16n8k8.row.col.f32.tf32.tf32.f32 "
        "{%0,%1,%2,%3}, {%4,%5,%6,%7}, {%8,%9}, {%0,%1,%2,%3};"
        : "+f"(d[0]), "+f"(d[1]), "+f"(d[2]), "+f"(d[3])
        : "r"(a[0]), "r"(a[1]), "r"(a[2]), "r"(a[3]),
          "r"(b[0]), "r"(b[1]));
}

// ===========================================================================
// Kernel 1: QKV projection via mma.sync tf32 (unchanged from R3).
// ===========================================================================
#define NCH 24   // 768 / 32

#define AS_STRIDE 36
#define BS_STRIDE 132
#define AS_BUF (128 * AS_STRIDE)
#define BS_BUF (32 * BS_STRIDE)
#define QKV_SMEM ((2 * AS_BUF + 2 * BS_BUF) * 4)

__global__ __launch_bounds__(256) void qkv_mma_kernel(
    const float* __restrict__ x,
    const float* __restrict__ Wq,
    const float* __restrict__ Wk,
    const float* __restrict__ Wv)
{
    extern __shared__ uint32_t sm_u[];
    uint32_t* As = sm_u;                  // [2][128][36]
    uint32_t* Bs = sm_u + 2 * AS_BUF;     // [2][32][132]

    const int tid  = threadIdx.x;
    const int wid  = tid >> 5;
    const int lane = tid & 31;
    const int g = lane >> 2;
    const int t = lane & 3;
    const int wr = wid & 3;
    const int wc = wid >> 2;
    const int m0 = blockIdx.x * 128;

    const float* W   = (blockIdx.y == 0) ? Wq : (blockIdx.y == 1) ? Wk : Wv;
    float*       outw = (blockIdx.y == 0) ? g_q : (blockIdx.y == 1) ? g_k : g_v;

    float acc[2][8][4];
    #pragma unroll
    for (int mt = 0; mt < 2; mt++)
        #pragma unroll
        for (int nt = 0; nt < 8; nt++)
            #pragma unroll
            for (int e = 0; e < 4; e++) acc[mt][nt][e] = 0.0f;

    float4 ra[4], rb[4];

    {
        const float* xg = x + (size_t)m0 * CC;
        #pragma unroll
        for (int p = 0; p < 4; p++) {
            int idx = tid + p * 256;
            int m = idx >> 3, k4 = (idx & 7) << 2;
            ra[p] = *reinterpret_cast<const float4*>(&xg[(size_t)m * CC + k4]);
            int k = idx >> 5, n4 = (idx & 31) << 2;
            rb[p] = *reinterpret_cast<const float4*>(&W[(size_t)k * HH + n4]);
        }
        #pragma unroll
        for (int p = 0; p < 4; p++) {
            int idx = tid + p * 256;
            int m = idx >> 3, k4 = (idx & 7) << 2;
            uint32_t* d = &As[m * AS_STRIDE + k4];
            d[0] = f2tf(ra[p].x); d[1] = f2tf(ra[p].y);
            d[2] = f2tf(ra[p].z); d[3] = f2tf(ra[p].w);
            int k = idx >> 5, n4 = (idx & 31) << 2;
            uint32_t* e = &Bs[k * BS_STRIDE + n4];
            e[0] = f2tf(rb[p].x); e[1] = f2tf(rb[p].y);
            e[2] = f2tf(rb[p].z); e[3] = f2tf(rb[p].w);
        }
    }
    __syncthreads();

    for (int c = 0; c < NCH; c++) {
        const int buf = c & 1;

        if (c + 1 < NCH) {
            const float* xg = x + (size_t)m0 * CC + (c + 1) * 32;
            const float* wg = W + (size_t)(c + 1) * 32 * HH;
            #pragma unroll
            for (int p = 0; p < 4; p++) {
                int idx = tid + p * 256;
                int m = idx >> 3, k4 = (idx & 7) << 2;
                ra[p] = *reinterpret_cast<const float4*>(&xg[(size_t)m * CC + k4]);
                int k = idx >> 5, n4 = (idx & 31) << 2;
                rb[p] = *reinterpret_cast<const float4*>(&wg[(size_t)k * HH + n4]);
            }
        }

        const uint32_t* Ab = As + buf * AS_BUF;
        const uint32_t* Bb = Bs + buf * BS_BUF;
        #pragma unroll
        for (int ks = 0; ks < 4; ks++) {
            uint32_t afr[2][4];
            #pragma unroll
            for (int mt = 0; mt < 2; mt++) {
                int rbase = wr * 32 + mt * 16;
                int k = ks * 8 + t;
                afr[mt][0] = Ab[(rbase + g)     * AS_STRIDE + k];
                afr[mt][1] = Ab[(rbase + g + 8) * AS_STRIDE + k];
                afr[mt][2] = Ab[(rbase + g)     * AS_STRIDE + k + 4];
                afr[mt][3] = Ab[(rbase + g + 8) * AS_STRIDE + k + 4];
            }
            #pragma unroll
            for (int nt = 0; nt < 8; nt++) {
                int n = wc * 64 + nt * 8 + g;
                uint32_t bfr[2];
                bfr[0] = Bb[(ks * 8 + t)     * BS_STRIDE + n];
                bfr[1] = Bb[(ks * 8 + t + 4) * BS_STRIDE + n];
                mma8(acc[0][nt], afr[0], bfr);
                mma8(acc[1][nt], afr[1], bfr);
            }
        }

        if (c + 1 < NCH) {
            uint32_t* Ad = As + ((c + 1) & 1) * AS_BUF;
            uint32_t* Bd = Bs + ((c + 1) & 1) * BS_BUF;
            #pragma unroll
            for (int p = 0; p < 4; p++) {
                int idx = tid + p * 256;
                int m = idx >> 3, k4 = (idx & 7) << 2;
                uint32_t* d = &Ad[m * AS_STRIDE + k4];
                d[0] = f2tf(ra[p].x); d[1] = f2tf(ra[p].y);
                d[2] = f2tf(ra[p].z); d[3] = f2tf(ra[p].w);
                int k = idx >> 5, n4 = (idx & 31) << 2;
                uint32_t* e = &Bd[k * BS_STRIDE + n4];
                e[0] = f2tf(rb[p].x); e[1] = f2tf(rb[p].y);
                e[2] = f2tf(rb[p].z); e[3] = f2tf(rb[p].w);
            }
        }
        __syncthreads();
    }

    #pragma unroll
    for (int mt = 0; mt < 2; mt++) {
        int r0 = m0 + wr * 32 + mt * 16 + g;
        #pragma unroll
        for (int nt = 0; nt < 8; nt++) {
            int col = wc * 64 + nt * 8 + 2 * t;
            *reinterpret_cast<float2*>(&outw[(size_t)r0 * HH + col]) =
                make_float2(acc[mt][nt][0], acc[mt][nt][1]);
            *reinterpret_cast<float2*>(&outw[(size_t)(r0 + 8) * HH + col]) =
                make_float2(acc[mt][nt][2], acc[mt][nt][3]);
        }
    }
}

// ===========================================================================
// Kernel 2: register-resident causal flash attention (FA2-style).
// CTA = 128 threads (4 warps), Q tile 64 rows; warp owns 16 full rows.
// Q fragments register-resident (scale folded in); softmax + S->P entirely
// in registers (quad shuffles); smem only K (stride 132) and V (stride 136).
// ===========================================================================
#define KS_STRIDE 132
#define VS_STRIDE 136
#define ATTN_SMEM ((64 * KS_STRIDE + 64 * VS_STRIDE) * 4)   // 68608 B

__global__ __launch_bounds__(128, 2) void attn_fa2_kernel(float* __restrict__ out)
{
    extern __shared__ float smf[];
    float* Ks = smf;                     // [64][132] (also Q staging)
    float* Vs = Ks + 64 * KS_STRIDE;     // [64][136]
    uint32_t* Ksu = reinterpret_cast<uint32_t*>(Ks);
    uint32_t* Vsu = reinterpret_cast<uint32_t*>(Vs);

    const int b  = blockIdx.y;
    const int qt = (int)gridDim.x - 1 - (int)blockIdx.x;   // heavy tiles first
    const int q0 = qt * 64;
    const int tid  = threadIdx.x;
    const int wid  = tid >> 5;
    const int lane = tid & 31;
    const int g = lane >> 2;
    const int t = lane & 3;

    const int r0l = wid * 16 + g;        // local row (slot 0/1)
    const int r1l = r0l + 8;             // local row (slot 2/3)

    const float scale = 0.03608439182435161f;  // 768^-0.5

    // ---- stage Q (scaled, tf32) into Ks, then grab fragments ----
    {
        const float* qg = g_q + ((size_t)b * TT + q0) * HH;
        #pragma unroll
        for (int p = 0; p < 16; p++) {
            int idx = tid + p * 128;
            int r = idx >> 5, c4 = (idx & 31) << 2;
            float4 v = *reinterpret_cast<const float4*>(&qg[(size_t)r * HH + c4]);
            uint32_t* d = &Ksu[r * KS_STRIDE + c4];
            d[0] = f2tf(v.x * scale); d[1] = f2tf(v.y * scale);
            d[2] = f2tf(v.z * scale); d[3] = f2tf(v.w * scale);
        }
    }
    __syncthreads();

    uint32_t qfr[16][4];
    #pragma unroll
    for (int ks = 0; ks < 16; ks++) {
        const int k = ks * 8 + t;
        qfr[ks][0] = Ksu[r0l * KS_STRIDE + k];
        qfr[ks][1] = Ksu[r1l * KS_STRIDE + k];
        qfr[ks][2] = Ksu[r0l * KS_STRIDE + k + 4];
        qfr[ks][3] = Ksu[r1l * KS_STRIDE + k + 4];
    }

    float m0 = -INFINITY, m1 = -INFINITY, l0 = 0.0f, l1 = 0.0f;
    float oacc[16][4];
    #pragma unroll
    for (int nt = 0; nt < 16; nt++)
        #pragma unroll
        for (int e = 0; e < 4; e++) oacc[nt][e] = 0.0f;

    const uint32_t srcA = (lane & 28) | (t >> 1);
    const uint32_t srcB = srcA + 2;

    const int nkt = qt + 1;
    for (int kt = 0; kt < nkt; kt++) {
        __syncthreads();  // previous tile's compute done (and Q frags loaded)

        // ---- stage K (stride 132) and V (stride 136), tf32 ----
        {
            const float* kg = g_k + ((size_t)b * TT + (size_t)kt * 64) * HH;
            const float* vg = g_v + ((size_t)b * TT + (size_t)kt * 64) * HH;
            #pragma unroll
            for (int p = 0; p < 16; p++) {
                int idx = tid + p * 128;
                int r = idx >> 5, c4 = (idx & 31) << 2;
                float4 kv = *reinterpret_cast<const float4*>(&kg[(size_t)r * HH + c4]);
                float4 vv = *reinterpret_cast<const float4*>(&vg[(size_t)r * HH + c4]);
                uint32_t* dk = &Ksu[r * KS_STRIDE + c4];
                dk[0] = f2tf(kv.x); dk[1] = f2tf(kv.y);
                dk[2] = f2tf(kv.z); dk[3] = f2tf(kv.w);
                uint32_t* dv = &Vsu[r * VS_STRIDE + c4];
                dv[0] = f2tf(vv.x); dv[1] = f2tf(vv.y);
                dv[2] = f2tf(vv.z); dv[3] = f2tf(vv.w);
            }
        }
        __syncthreads();

        // ---- S = (scale*Q) K^T : warp rows r0l/r1l.., all 64 cols ----
        float sacc[8][4];
        #pragma unroll
        for (int nt = 0; nt < 8; nt++)
            #pragma unroll
            for (int e = 0; e < 4; e++) sacc[nt][e] = 0.0f;

        #pragma unroll
        for (int ks = 0; ks < 16; ks++) {
            const int k = ks * 8 + t;
            #pragma unroll
            for (int nt = 0; nt < 8; nt++) {
                const int n = nt * 8 + g;
                uint32_t bfr[2];
                bfr[0] = Ksu[n * KS_STRIDE + k];
                bfr[1] = Ksu[n * KS_STRIDE + k + 4];
                mma8(sacc[nt], qfr[ks], bfr);
            }
        }

        // ---- mask (diagonal tile) ----
        if (kt == qt) {
            #pragma unroll
            for (int nt = 0; nt < 8; nt++) {
                const int cl = nt * 8 + 2 * t;
                if (cl     > r0l) sacc[nt][0] = -INFINITY;
                if (cl + 1 > r0l) sacc[nt][1] = -INFINITY;
                if (cl     > r1l) sacc[nt][2] = -INFINITY;
                if (cl + 1 > r1l) sacc[nt][3] = -INFINITY;
            }
        }

        // ---- online softmax in registers ----
        float mx0 = -INFINITY, mx1 = -INFINITY;
        #pragma unroll
        for (int nt = 0; nt < 8; nt++) {
            mx0 = fmaxf(mx0, fmaxf(sacc[nt][0], sacc[nt][1]));
            mx1 = fmaxf(mx1, fmaxf(sacc[nt][2], sacc[nt][3]));
        }
        mx0 = fmaxf(mx0, __shfl_xor_sync(0xffffffffu, mx0, 1));
        mx0 = fmaxf(mx0, __shfl_xor_sync(0xffffffffu, mx0, 2));
        mx1 = fmaxf(mx1, __shfl_xor_sync(0xffffffffu, mx1, 1));
        mx1 = fmaxf(mx1, __shfl_xor_sync(0xffffffffu, mx1, 2));

        const float m0n = fmaxf(m0, mx0);
        const float m1n = fmaxf(m1, mx1);
        const float c0 = __expf(m0 - m0n);
        const float c1 = __expf(m1 - m1n);

        float s0 = 0.0f, s1 = 0.0f;
        #pragma unroll
        for (int nt = 0; nt < 8; nt++) {
            sacc[nt][0] = __expf(sacc[nt][0] - m0n);
            sacc[nt][1] = __expf(sacc[nt][1] - m0n);
            sacc[nt][2] = __expf(sacc[nt][2] - m1n);
            sacc[nt][3] = __expf(sacc[nt][3] - m1n);
            s0 += sacc[nt][0] + sacc[nt][1];
            s1 += sacc[nt][2] + sacc[nt][3];
        }
        s0 += __shfl_xor_sync(0xffffffffu, s0, 1);
        s0 += __shfl_xor_sync(0xffffffffu, s0, 2);
        s1 += __shfl_xor_sync(0xffffffffu, s1, 1);
        s1 += __shfl_xor_sync(0xffffffffu, s1, 2);

        l0 = l0 * c0 + s0;
        l1 = l1 * c1 + s1;
        m0 = m0n;
        m1 = m1n;

        // rescale O
        #pragma unroll
        for (int nt = 0; nt < 16; nt++) {
            oacc[nt][0] *= c0; oacc[nt][1] *= c0;
            oacc[nt][2] *= c1; oacc[nt][3] *= c1;
        }

        // ---- O += P V : P from registers via quad shuffles ----
        #pragma unroll
        for (int kk = 0; kk < 8; kk++) {
            float v0 = __shfl_sync(0xffffffffu, sacc[kk][0], srcA);
            float v1 = __shfl_sync(0xffffffffu, sacc[kk][1], srcA);
            float v2 = __shfl_sync(0xffffffffu, sacc[kk][2], srcA);
            float v3 = __shfl_sync(0xffffffffu, sacc[kk][3], srcA);
            float w0 = __shfl_sync(0xffffffffu, sacc[kk][0], srcB);
            float w1 = __shfl_sync(0xffffffffu, sacc[kk][1], srcB);
            float w2 = __shfl_sync(0xffffffffu, sacc[kk][2], srcB);
            float w3 = __shfl_sync(0xffffffffu, sacc[kk][3], srcB);
            uint32_t afr[4];
            afr[0] = f2tf((t & 1) ? v1 : v0);   // row g,   col kk*8+t
            afr[1] = f2tf((t & 1) ? v3 : v2);   // row g+8, col kk*8+t
            afr[2] = f2tf((t & 1) ? w1 : w0);   // row g,   col kk*8+t+4
            afr[3] = f2tf((t & 1) ? w3 : w2);   // row g+8, col kk*8+t+4

            const int k = kk * 8 + t;
            #pragma unroll
            for (int nt = 0; nt < 16; nt++) {
                const int n = nt * 8 + g;
                uint32_t bfr[2];
                bfr[0] = Vsu[k * VS_STRIDE + n];
                bfr[1] = Vsu[(k + 4) * VS_STRIDE + n];
                mma8(oacc[nt], afr, bfr);
            }
        }
    }

    // ---- epilogue ----
    const float inv0 = 1.0f / l0;
    const float inv1 = 1.0f / l1;
    float* og = out + ((size_t)b * TT + q0) * HH;
    #pragma unroll
    for (int nt = 0; nt < 16; nt++) {
        const int col = nt * 8 + 2 * t;
        *reinterpret_cast<float2*>(&og[(size_t)r0l * HH + col]) =
            make_float2(oacc[nt][0] * inv0, oacc[nt][1] * inv0);
        *reinterpret_cast<float2*>(&og[(size_t)r1l * HH + col]) =
            make_float2(oacc[nt][2] * inv1, oacc[nt][3] * inv1);
    }
}

// ===========================================================================
// Launch
// ===========================================================================
extern "C" void kernel_launch(void* const* d_in, const int* in_sizes, int n_in,
                              void* d_out, int out_size)
{
    const float* x  = (const float*)d_in[0];
    const float* Wq = (const float*)d_in[1];
    const float* Wk = (const float*)d_in[2];
    const float* Wv = (const float*)d_in[3];
    float* out = (float*)d_out;

    cudaFuncSetAttribute(qkv_mma_kernel,
                         cudaFuncAttributeMaxDynamicSharedMemorySize, QKV_SMEM);
    cudaFuncSetAttribute(attn_fa2_kernel,
                         cudaFuncAttributeMaxDynamicSharedMemorySize, ATTN_SMEM);

    qkv_mma_kernel<<<dim3(TT * BB / 128, 3), 256, QKV_SMEM>>>(x, Wq, Wk, Wv);
    attn_fa2_kernel<<<dim3(TT / 64, BB), 128, ATTN_SMEM>>>(out);
}

// round 6
// speedup vs baseline: 3.8979x; 1.0537x over previous
#include <cuda_runtime.h>
#include <cstdint>
#include <math.h>

#define BB 16
#define TT 2048
#define CC 768
#define HH 128

// Scratch for projected Q, K, V: [B][T][H] each.
// Values are stored ALREADY rna-rounded to tf32 (and Q pre-scaled), so the
// attention kernel can feed raw bits to tf32 mma with no further conversion.
__device__ float g_q[BB * TT * HH];
__device__ float g_k[BB * TT * HH];
__device__ float g_v[BB * TT * HH];

// ---------------------------------------------------------------------------
// helpers
// ---------------------------------------------------------------------------
__device__ __forceinline__ uint32_t f2tf(float f) {
    uint32_t u;
    asm("cvt.rna.tf32.f32 %0, %1;" : "=r"(u) : "f"(f));
    return u;
}

// D += A * B   (m16n8k8, tf32 inputs, fp32 accum)
__device__ __forceinline__ void mma8(float* d, const uint32_t* a, const uint32_t* b) {
    asm volatile(
        "mma.sync.aligned.m16n8k8.row.col.f32.tf32.tf32.f32 "
        "{%0,%1,%2,%3}, {%4,%5,%6,%7}, {%8,%9}, {%0,%1,%2,%3};"
        : "+f"(d[0]), "+f"(d[1]), "+f"(d[2]), "+f"(d[3])
        : "r"(a[0]), "r"(a[1]), "r"(a[2]), "r"(a[3]),
          "r"(b[0]), "r"(b[1]));
}

__device__ __forceinline__ void cp_async16(uint32_t smem_dst, const void* gmem_src) {
    asm volatile("cp.async.cg.shared.global [%0], [%1], 16;"
                 :: "r"(smem_dst), "l"(gmem_src) : "memory");
}
__device__ __forceinline__ void cp_async_commit() {
    asm volatile("cp.async.commit_group;" ::: "memory");
}
__device__ __forceinline__ void cp_async_wait_all() {
    asm volatile("cp.async.wait_group 0;" ::: "memory");
}

__device__ __forceinline__ uint32_t smem_u32(const void* p) {
    uint32_t a;
    asm("{ .reg .u64 t; cvta.to.shared.u64 t, %1; cvt.u32.u64 %0, t; }"
        : "=r"(a) : "l"(p));
    return a;
}

// ===========================================================================
// Kernel 1: QKV projection via mma.sync tf32.
// Scale folded into Wq staging; outputs stored tf32-rounded.
// ===========================================================================
#define NCH 24   // 768 / 32

#define AS_STRIDE 36
#define BS_STRIDE 132
#define AS_BUF (128 * AS_STRIDE)
#define BS_BUF (32 * BS_STRIDE)
#define QKV_SMEM ((2 * AS_BUF + 2 * BS_BUF) * 4)

__global__ __launch_bounds__(256) void qkv_mma_kernel(
    const float* __restrict__ x,
    const float* __restrict__ Wq,
    const float* __restrict__ Wk,
    const float* __restrict__ Wv)
{
    extern __shared__ uint32_t sm_u[];
    uint32_t* As = sm_u;                  // [2][128][36]
    uint32_t* Bs = sm_u + 2 * AS_BUF;     // [2][32][132]

    const int tid  = threadIdx.x;
    const int wid  = tid >> 5;
    const int lane = tid & 31;
    const int g = lane >> 2;
    const int t = lane & 3;
    const int wr = wid & 3;
    const int wc = wid >> 2;
    const int m0 = blockIdx.x * 128;

    const float* W   = (blockIdx.y == 0) ? Wq : (blockIdx.y == 1) ? Wk : Wv;
    float*       outw = (blockIdx.y == 0) ? g_q : (blockIdx.y == 1) ? g_k : g_v;
    // softmax scale folded into Wq
    const float wscale = (blockIdx.y == 0) ? 0.03608439182435161f : 1.0f;

    float acc[2][8][4];
    #pragma unroll
    for (int mt = 0; mt < 2; mt++)
        #pragma unroll
        for (int nt = 0; nt < 8; nt++)
            #pragma unroll
            for (int e = 0; e < 4; e++) acc[mt][nt][e] = 0.0f;

    float4 ra[4], rb[4];

    {
        const float* xg = x + (size_t)m0 * CC;
        #pragma unroll
        for (int p = 0; p < 4; p++) {
            int idx = tid + p * 256;
            int m = idx >> 3, k4 = (idx & 7) << 2;
            ra[p] = *reinterpret_cast<const float4*>(&xg[(size_t)m * CC + k4]);
            int k = idx >> 5, n4 = (idx & 31) << 2;
            rb[p] = *reinterpret_cast<const float4*>(&W[(size_t)k * HH + n4]);
        }
        #pragma unroll
        for (int p = 0; p < 4; p++) {
            int idx = tid + p * 256;
            int m = idx >> 3, k4 = (idx & 7) << 2;
            uint32_t* d = &As[m * AS_STRIDE + k4];
            d[0] = f2tf(ra[p].x); d[1] = f2tf(ra[p].y);
            d[2] = f2tf(ra[p].z); d[3] = f2tf(ra[p].w);
            int k = idx >> 5, n4 = (idx & 31) << 2;
            uint32_t* e = &Bs[k * BS_STRIDE + n4];
            e[0] = f2tf(rb[p].x * wscale); e[1] = f2tf(rb[p].y * wscale);
            e[2] = f2tf(rb[p].z * wscale); e[3] = f2tf(rb[p].w * wscale);
        }
    }
    __syncthreads();

    for (int c = 0; c < NCH; c++) {
        const int buf = c & 1;

        if (c + 1 < NCH) {
            const float* xg = x + (size_t)m0 * CC + (c + 1) * 32;
            const float* wg = W + (size_t)(c + 1) * 32 * HH;
            #pragma unroll
            for (int p = 0; p < 4; p++) {
                int idx = tid + p * 256;
                int m = idx >> 3, k4 = (idx & 7) << 2;
                ra[p] = *reinterpret_cast<const float4*>(&xg[(size_t)m * CC + k4]);
                int k = idx >> 5, n4 = (idx & 31) << 2;
                rb[p] = *reinterpret_cast<const float4*>(&wg[(size_t)k * HH + n4]);
            }
        }

        const uint32_t* Ab = As + buf * AS_BUF;
        const uint32_t* Bb = Bs + buf * BS_BUF;
        #pragma unroll
        for (int ks = 0; ks < 4; ks++) {
            uint32_t afr[2][4];
            #pragma unroll
            for (int mt = 0; mt < 2; mt++) {
                int rbase = wr * 32 + mt * 16;
                int k = ks * 8 + t;
                afr[mt][0] = Ab[(rbase + g)     * AS_STRIDE + k];
                afr[mt][1] = Ab[(rbase + g + 8) * AS_STRIDE + k];
                afr[mt][2] = Ab[(rbase + g)     * AS_STRIDE + k + 4];
                afr[mt][3] = Ab[(rbase + g + 8) * AS_STRIDE + k + 4];
            }
            #pragma unroll
            for (int nt = 0; nt < 8; nt++) {
                int n = wc * 64 + nt * 8 + g;
                uint32_t bfr[2];
                bfr[0] = Bb[(ks * 8 + t)     * BS_STRIDE + n];
                bfr[1] = Bb[(ks * 8 + t + 4) * BS_STRIDE + n];
                mma8(acc[0][nt], afr[0], bfr);
                mma8(acc[1][nt], afr[1], bfr);
            }
        }

        if (c + 1 < NCH) {
            uint32_t* Ad = As + ((c + 1) & 1) * AS_BUF;
            uint32_t* Bd = Bs + ((c + 1) & 1) * BS_BUF;
            #pragma unroll
            for (int p = 0; p < 4; p++) {
                int idx = tid + p * 256;
                int m = idx >> 3, k4 = (idx & 7) << 2;
                uint32_t* d = &Ad[m * AS_STRIDE + k4];
                d[0] = f2tf(ra[p].x); d[1] = f2tf(ra[p].y);
                d[2] = f2tf(ra[p].z); d[3] = f2tf(ra[p].w);
                int k = idx >> 5, n4 = (idx & 31) << 2;
                uint32_t* e = &Bd[k * BS_STRIDE + n4];
                e[0] = f2tf(rb[p].x * wscale); e[1] = f2tf(rb[p].y * wscale);
                e[2] = f2tf(rb[p].z * wscale); e[3] = f2tf(rb[p].w * wscale);
            }
        }
        __syncthreads();
    }

    // epilogue: store tf32-rounded bits
    #pragma unroll
    for (int mt = 0; mt < 2; mt++) {
        int r0 = m0 + wr * 32 + mt * 16 + g;
        #pragma unroll
        for (int nt = 0; nt < 8; nt++) {
            int col = wc * 64 + nt * 8 + 2 * t;
            *reinterpret_cast<float2*>(&outw[(size_t)r0 * HH + col]) =
                make_float2(__uint_as_float(f2tf(acc[mt][nt][0])),
                            __uint_as_float(f2tf(acc[mt][nt][1])));
            *reinterpret_cast<float2*>(&outw[(size_t)(r0 + 8) * HH + col]) =
                make_float2(__uint_as_float(f2tf(acc[mt][nt][2])),
                            __uint_as_float(f2tf(acc[mt][nt][3])));
        }
    }
}

// ===========================================================================
// Kernel 2: register-resident causal flash attention with cp.async pipeline.
// Split-phase: V[i] streams during S(i) compute; K[i+1] streams during PV(i).
// All global data already tf32-exact -> no conversions in the hot loop.
//
// Tile = 64 rows x 128 cols fp32 = 2048 float4 chunks; 128 threads -> 16
// chunks each: idx = tid + p*128, r = idx>>5 (0..63), c = (idx&31)*4.
// ===========================================================================
#define KS_STRIDE 132
#define VS_STRIDE 136
#define ATTN_SMEM ((64 * KS_STRIDE + 64 * VS_STRIDE) * 4)   // 68608 B

__global__ __launch_bounds__(128, 2) void attn_fa2_kernel(float* __restrict__ out)
{
    extern __shared__ float smf[];
    float* Ks = smf;                     // [64][132]
    float* Vs = Ks + 64 * KS_STRIDE;     // [64][136]  (also Q staging)
    uint32_t* Ksu = reinterpret_cast<uint32_t*>(Ks);
    uint32_t* Vsu = reinterpret_cast<uint32_t*>(Vs);
    const uint32_t Ks_a = smem_u32(Ks);
    const uint32_t Vs_a = smem_u32(Vs);

    const int b  = blockIdx.y;
    const int qt = (int)gridDim.x - 1 - (int)blockIdx.x;   // heavy tiles first
    const int q0 = qt * 64;
    const int tid  = threadIdx.x;
    const int wid  = tid >> 5;
    const int lane = tid & 31;
    const int g = lane >> 2;
    const int t = lane & 3;

    const int r0l = wid * 16 + g;
    const int r1l = r0l + 8;

    const float* kbase = g_k + (size_t)b * TT * HH;
    const float* vbase = g_v + (size_t)b * TT * HH;

    // ---- prologue: start K[0] async load; stage Q through Vs ----
    {
        const float* kg = kbase;
        #pragma unroll
        for (int p = 0; p < 16; p++) {
            int idx = tid + p * 128;
            int r = idx >> 5, c = (idx & 31) << 2;
            cp_async16(Ks_a + (uint32_t)(r * KS_STRIDE + c) * 4,
                       kg + (size_t)r * HH + c);
        }
        cp_async_commit();
    }
    {
        const float* qg = g_q + ((size_t)b * TT + q0) * HH;
        #pragma unroll
        for (int p = 0; p < 16; p++) {
            int idx = tid + p * 128;
            int r = idx >> 5, c4 = (idx & 31) << 2;
            *reinterpret_cast<float4*>(&Vs[r * VS_STRIDE + c4]) =
                *reinterpret_cast<const float4*>(&qg[(size_t)r * HH + c4]);
        }
    }
    __syncthreads();

    uint32_t qfr[16][4];
    #pragma unroll
    for (int ks = 0; ks < 16; ks++) {
        const int k = ks * 8 + t;
        qfr[ks][0] = Vsu[r0l * VS_STRIDE + k];
        qfr[ks][1] = Vsu[r1l * VS_STRIDE + k];
        qfr[ks][2] = Vsu[r0l * VS_STRIDE + k + 4];
        qfr[ks][3] = Vsu[r1l * VS_STRIDE + k + 4];
    }

    float m0 = -INFINITY, m1 = -INFINITY, l0 = 0.0f, l1 = 0.0f;
    float oacc[16][4];
    #pragma unroll
    for (int nt = 0; nt < 16; nt++)
        #pragma unroll
        for (int e = 0; e < 4; e++) oacc[nt][e] = 0.0f;

    const uint32_t srcA = (lane & 28) | (t >> 1);
    const uint32_t srcB = srcA + 2;

    const int nkt = qt + 1;
    for (int kt = 0; kt < nkt; kt++) {
        // ---- K[kt] arrived; all threads past qfr / previous-V reads ----
        cp_async_wait_all();
        __syncthreads();

        // ---- start V[kt] load (overlaps S compute) ----
        {
            const float* vg = vbase + (size_t)kt * 64 * HH;
            #pragma unroll
            for (int p = 0; p < 16; p++) {
                int idx = tid + p * 128;
                int r = idx >> 5, c = (idx & 31) << 2;
                cp_async16(Vs_a + (uint32_t)(r * VS_STRIDE + c) * 4,
                           vg + (size_t)r * HH + c);
            }
            cp_async_commit();
        }

        // ---- S = Q K^T ----
        float sacc[8][4];
        #pragma unroll
        for (int nt = 0; nt < 8; nt++)
            #pragma unroll
            for (int e = 0; e < 4; e++) sacc[nt][e] = 0.0f;

        #pragma unroll
        for (int ks = 0; ks < 16; ks++) {
            const int k = ks * 8 + t;
            #pragma unroll
            for (int nt = 0; nt < 8; nt++) {
                const int n = nt * 8 + g;
                uint32_t bfr[2];
                bfr[0] = Ksu[n * KS_STRIDE + k];
                bfr[1] = Ksu[n * KS_STRIDE + k + 4];
                mma8(sacc[nt], qfr[ks], bfr);
            }
        }

        // ---- mask (diagonal tile) ----
        if (kt == qt) {
            #pragma unroll
            for (int nt = 0; nt < 8; nt++) {
                const int cl = nt * 8 + 2 * t;
                if (cl     > r0l) sacc[nt][0] = -INFINITY;
                if (cl + 1 > r0l) sacc[nt][1] = -INFINITY;
                if (cl     > r1l) sacc[nt][2] = -INFINITY;
                if (cl + 1 > r1l) sacc[nt][3] = -INFINITY;
            }
        }

        // ---- online softmax in registers ----
        float mx0 = -INFINITY, mx1 = -INFINITY;
        #pragma unroll
        for (int nt = 0; nt < 8; nt++) {
            mx0 = fmaxf(mx0, fmaxf(sacc[nt][0], sacc[nt][1]));
            mx1 = fmaxf(mx1, fmaxf(sacc[nt][2], sacc[nt][3]));
        }
        mx0 = fmaxf(mx0, __shfl_xor_sync(0xffffffffu, mx0, 1));
        mx0 = fmaxf(mx0, __shfl_xor_sync(0xffffffffu, mx0, 2));
        mx1 = fmaxf(mx1, __shfl_xor_sync(0xffffffffu, mx1, 1));
        mx1 = fmaxf(mx1, __shfl_xor_sync(0xffffffffu, mx1, 2));

        const float m0n = fmaxf(m0, mx0);
        const float m1n = fmaxf(m1, mx1);
        const float c0 = __expf(m0 - m0n);
        const float c1 = __expf(m1 - m1n);

        float s0 = 0.0f, s1 = 0.0f;
        #pragma unroll
        for (int nt = 0; nt < 8; nt++) {
            sacc[nt][0] = __expf(sacc[nt][0] - m0n);
            sacc[nt][1] = __expf(sacc[nt][1] - m0n);
            sacc[nt][2] = __expf(sacc[nt][2] - m1n);
            sacc[nt][3] = __expf(sacc[nt][3] - m1n);
            s0 += sacc[nt][0] + sacc[nt][1];
            s1 += sacc[nt][2] + sacc[nt][3];
        }
        s0 += __shfl_xor_sync(0xffffffffu, s0, 1);
        s0 += __shfl_xor_sync(0xffffffffu, s0, 2);
        s1 += __shfl_xor_sync(0xffffffffu, s1, 1);
        s1 += __shfl_xor_sync(0xffffffffu, s1, 2);

        l0 = l0 * c0 + s0;
        l1 = l1 * c1 + s1;
        m0 = m0n;
        m1 = m1n;

        #pragma unroll
        for (int nt = 0; nt < 16; nt++) {
            oacc[nt][0] *= c0; oacc[nt][1] *= c0;
            oacc[nt][2] *= c1; oacc[nt][3] *= c1;
        }

        // ---- V[kt] arrived; all warps done reading K ----
        cp_async_wait_all();
        __syncthreads();

        // ---- start K[kt+1] load (overlaps PV compute) ----
        if (kt + 1 < nkt) {
            const float* kg = kbase + (size_t)(kt + 1) * 64 * HH;
            #pragma unroll
            for (int p = 0; p < 16; p++) {
                int idx = tid + p * 128;
                int r = idx >> 5, c = (idx & 31) << 2;
                cp_async16(Ks_a + (uint32_t)(r * KS_STRIDE + c) * 4,
                           kg + (size_t)r * HH + c);
            }
            cp_async_commit();
        }

        // ---- O += P V : P from registers via quad shuffles ----
        #pragma unroll
        for (int kk = 0; kk < 8; kk++) {
            float v0 = __shfl_sync(0xffffffffu, sacc[kk][0], srcA);
            float v1 = __shfl_sync(0xffffffffu, sacc[kk][1], srcA);
            float v2 = __shfl_sync(0xffffffffu, sacc[kk][2], srcA);
            float v3 = __shfl_sync(0xffffffffu, sacc[kk][3], srcA);
            float w0 = __shfl_sync(0xffffffffu, sacc[kk][0], srcB);
            float w1 = __shfl_sync(0xffffffffu, sacc[kk][1], srcB);
            float w2 = __shfl_sync(0xffffffffu, sacc[kk][2], srcB);
            float w3 = __shfl_sync(0xffffffffu, sacc[kk][3], srcB);
            uint32_t afr[4];
            afr[0] = f2tf((t & 1) ? v1 : v0);
            afr[1] = f2tf((t & 1) ? v3 : v2);
            afr[2] = f2tf((t & 1) ? w1 : w0);
            afr[3] = f2tf((t & 1) ? w3 : w2);

            const int k = kk * 8 + t;
            #pragma unroll
            for (int nt = 0; nt < 16; nt++) {
                const int n = nt * 8 + g;
                uint32_t bfr[2];
                bfr[0] = Vsu[k * VS_STRIDE + n];
                bfr[1] = Vsu[(k + 4) * VS_STRIDE + n];
                mma8(oacc[nt], afr, bfr);
            }
        }
    }

    // ---- epilogue ----
    const float inv0 = 1.0f / l0;
    const float inv1 = 1.0f / l1;
    float* og = out + ((size_t)b * TT + q0) * HH;
    #pragma unroll
    for (int nt = 0; nt < 16; nt++) {
        const int col = nt * 8 + 2 * t;
        *reinterpret_cast<float2*>(&og[(size_t)r0l * HH + col]) =
            make_float2(oacc[nt][0] * inv0, oacc[nt][1] * inv0);
        *reinterpret_cast<float2*>(&og[(size_t)r1l * HH + col]) =
            make_float2(oacc[nt][2] * inv1, oacc[nt][3] * inv1);
    }
}

// ===========================================================================
// Launch
// ===========================================================================
extern "C" void kernel_launch(void* const* d_in, const int* in_sizes, int n_in,
                              void* d_out, int out_size)
{
    const float* x  = (const float*)d_in[0];
    const float* Wq = (const float*)d_in[1];
    const float* Wk = (const float*)d_in[2];
    const float* Wv = (const float*)d_in[3];
    float* out = (float*)d_out;

    cudaFuncSetAttribute(qkv_mma_kernel,
                         cudaFuncAttributeMaxDynamicSharedMemorySize, QKV_SMEM);
    cudaFuncSetAttribute(attn_fa2_kernel,
                         cudaFuncAttributeMaxDynamicSharedMemorySize, ATTN_SMEM);

    qkv_mma_kernel<<<dim3(TT * BB / 128, 3), 256, QKV_SMEM>>>(x, Wq, Wk, Wv);
    attn_fa2_kernel<<<dim3(TT / 64, BB), 128, ATTN_SMEM>>>(out);
}